// round 12
// baseline (speedup 1.0000x reference)
#include <cuda_runtime.h>
#include <cuda_fp16.h>
#include <cstdint>
#include <math.h>

#define DIMC  512
#define NH    8
#define HD    64
#define NB    8
#define NSEQ  1024
#define QK_SCALE 0.125f

// fp16 scratch, pair-permuted per 16-block: [0,1,8,9,2,3,10,11,4,5,12,13,6,7,14,15]
__device__ __half g_q[NB * NH * NSEQ * HD];      // [bh][n][d]  perm, *0.125
__device__ __half g_k[NB * NH * NSEQ * HD];      // [bh][n][d]  perm
__device__ __half g_vt[NB * NH * HD * NSEQ];     // [bh][d][kv] perm over kv
__device__ __half g_attnp[NB * NSEQ * DIMC];     // [b*n][c]    perm
__device__ __half g_xp[NB * NSEQ * DIMC];
__device__ __half g_wqkvp[3 * DIMC * DIMC];
__device__ __half g_wprojp[DIMC * DIMC];

__device__ __forceinline__ int perm16(int d) {
    return (((d & 7) >> 1) << 2) + (((d >> 3) & 1) << 1) + (d & 1);
}
__device__ __forceinline__ uint32_t packh(float lo, float hi) {
    __half2 h = __floats2half2_rn(lo, hi);
    return *(uint32_t*)&h;
}
__device__ __forceinline__ void mma16(float* d, const uint32_t* a, uint32_t b0, uint32_t b1) {
    asm volatile(
        "mma.sync.aligned.m16n8k16.row.col.f32.f16.f16.f32 "
        "{%0,%1,%2,%3}, {%4,%5,%6,%7}, {%8,%9}, {%0,%1,%2,%3};"
        : "+f"(d[0]), "+f"(d[1]), "+f"(d[2]), "+f"(d[3])
        : "r"(a[0]), "r"(a[1]), "r"(a[2]), "r"(a[3]), "r"(b0), "r"(b1));
}
__device__ __forceinline__ uint32_t smem_u32(const void* p) {
    uint32_t a;
    asm("{ .reg .u64 t; cvta.to.shared.u64 t, %1; cvt.u32.u64 %0, t; }" : "=r"(a) : "l"(p));
    return a;
}
#define CP16(d, s) asm volatile("cp.async.cg.shared.global [%0], [%1], 16;" :: "r"(d), "l"(s))
#define CPCOMMIT() asm volatile("cp.async.commit_group;" ::: "memory")
#define CPWAIT1()  asm volatile("cp.async.wait_group 1;" ::: "memory")
#define CPWAIT0()  asm volatile("cp.async.wait_group 0;" ::: "memory")

// ===========================================================================
// Pre-pass: fp32 -> fp16 permuted.
// ===========================================================================
__global__ __launch_bounds__(256) void preperm(const float* __restrict__ x,
                                               const float* __restrict__ wq,
                                               const float* __restrict__ wp) {
    int idx = blockIdx.x * 256 + threadIdx.x;
    if (idx >= 10240 * 32) return;
    int row = idx >> 5, blk = idx & 31;
    const float* src; __half* dst; int r;
    if (row < 8192)      { r = row;        src = x  + (size_t)r * 512; dst = g_xp    + (size_t)r * 512; }
    else if (row < 9728) { r = row - 8192; src = wq + (size_t)r * 512; dst = g_wqkvp + (size_t)r * 512; }
    else                 { r = row - 9728; src = wp + (size_t)r * 512; dst = g_wprojp + (size_t)r * 512; }
    float f[16];
    const float4* s4 = (const float4*)(src + blk * 16);
#pragma unroll
    for (int i = 0; i < 4; i++) { float4 v = s4[i]; f[4*i] = v.x; f[4*i+1] = v.y; f[4*i+2] = v.z; f[4*i+3] = v.w; }
    uint32_t u[8];
#pragma unroll
    for (int k = 0; k < 8; k++) {
        int e = 2 * (k >> 1) + 8 * (k & 1);
        u[k] = packh(f[e], f[e + 1]);
    }
    uint4* d4 = (uint4*)(dst + blk * 16);
    d4[0] = make_uint4(u[0], u[1], u[2], u[3]);
    d4[1] = make_uint4(u[4], u[5], u[6], u[7]);
}

// ===========================================================================
// fp16 GEMM: CTA 128x128, 256 thr, 8 warps (2x4), warp tile 64x32,
// BK=64 halfs (8 iterations), 2-stage cp.async, pitch 80 halfs.
// ===========================================================================
#define GP 80                                // halfs (64 data + 16 pad)
#define GSTAGE_B (256 * GP * 2)              // 40960 B per stage
#define GEMM_SMEM (2 * GSTAGE_B)             // 81920 B

__global__ __launch_bounds__(256, 2) void mma_gemm(const float* __restrict__ Bvec,
                                                   float* __restrict__ Out,
                                                   int mode) {
    extern __shared__ __half smh[];
    const uint32_t sbase = smem_u32(smh);
    const int tid = threadIdx.x, wid = tid >> 5, lane = tid & 31;
    const int g = lane >> 2, th = lane & 3;
    const int wm = wid >> 2, wn = wid & 3;
    const int bm = blockIdx.x * 128, bn = blockIdx.y * 128;

    const __half* Ap = mode ? g_attnp : g_xp;
    const __half* Wp = mode ? g_wprojp : g_wqkvp;
    const int lrow = tid & 127, side = tid >> 7;
    const __half* gsrc = side ? (Wp + (size_t)(bn + lrow) * 512)
                              : (Ap + (size_t)(bm + lrow) * 512);
    const uint32_t dst0 = sbase + (uint32_t)((side * 128 + lrow) * GP) * 2;

    int offA0[4], offA1[4], offB[4];
#pragma unroll
    for (int ma = 0; ma < 4; ma++) {
        int ra = wm * 64 + ma * 16 + g;
        offA0[ma] = ra * GP + 4 * th;
        offA1[ma] = (ra + 8) * GP + 4 * th;
    }
#pragma unroll
    for (int nb = 0; nb < 4; nb++)
        offB[nb] = 128 * GP + (wn * 32 + nb * 8 + g) * GP + 4 * th;

    float acc[4][4][4];
#pragma unroll
    for (int i = 0; i < 4; i++)
#pragma unroll
        for (int j = 0; j < 4; j++)
#pragma unroll
            for (int q = 0; q < 4; q++) acc[i][j][q] = 0.0f;

#define G_ISSUE(I)                                                        \
    {                                                                     \
        uint32_t _d = dst0 + ((I) & 1) * GSTAGE_B;                        \
        const __half* _s = gsrc + (I) * 64;                               \
        _Pragma("unroll")                                                 \
        for (int c = 0; c < 8; c++) CP16(_d + c * 16, _s + c * 8);        \
        CPCOMMIT();                                                       \
    }

    G_ISSUE(0);
    G_ISSUE(1);

    for (int i = 0; i < 8; i++) {
        if (i < 7) CPWAIT1(); else CPWAIT0();
        __syncthreads();
        const __half* S0 = smh + (i & 1) * (GSTAGE_B / 2);
#pragma unroll
        for (int s = 0; s < 4; s++) {
            uint32_t Af[4][4];
#pragma unroll
            for (int ma = 0; ma < 4; ma++) {
                uint2 lo = *(const uint2*)(S0 + offA0[ma] + 16 * s);
                uint2 hi = *(const uint2*)(S0 + offA1[ma] + 16 * s);
                Af[ma][0] = lo.x; Af[ma][1] = hi.x; Af[ma][2] = lo.y; Af[ma][3] = hi.y;
            }
#pragma unroll
            for (int nb = 0; nb < 4; nb++) {
                uint2 bv = *(const uint2*)(S0 + offB[nb] + 16 * s);
#pragma unroll
                for (int ma = 0; ma < 4; ma++) mma16(acc[ma][nb], Af[ma], bv.x, bv.y);
            }
        }
        __syncthreads();
        if (i + 2 < 8) G_ISSUE(i + 2);
    }

#pragma unroll
    for (int ma = 0; ma < 4; ma++) {
#pragma unroll
        for (int nb = 0; nb < 4; nb++) {
            int r0 = bm + wm * 64 + ma * 16 + g;
            int cg = bn + wn * 32 + nb * 8 + 2 * th;
#pragma unroll
            for (int e = 0; e < 2; e++) {
                int rr = r0 + e * 8;
                float v0 = acc[ma][nb][2 * e], v1 = acc[ma][nb][2 * e + 1];
                if (mode == 0) {
                    int bb = rr >> 10, n = rr & 1023;
                    int which = cg >> 9, hh = (cg >> 6) & 7, dd = cg & 63;
                    size_t bh = (size_t)(bb * NH + hh);
                    if (which == 0) {
                        size_t off = (bh * NSEQ + n) * HD + (dd & ~15) + perm16(dd & 15);
                        *(__half2*)(g_q + off) = __floats2half2_rn(v0 * QK_SCALE, v1 * QK_SCALE);
                    } else if (which == 1) {
                        size_t off = (bh * NSEQ + n) * HD + (dd & ~15) + perm16(dd & 15);
                        *(__half2*)(g_k + off) = __floats2half2_rn(v0, v1);
                    } else {
                        size_t vb = (bh * HD + dd) * NSEQ + (n & ~15) + perm16(n & 15);
                        g_vt[vb]        = __float2half_rn(v0);
                        g_vt[vb + NSEQ] = __float2half_rn(v1);
                    }
                } else {
                    float2 bv = *(const float2*)(Bvec + cg);
                    float2 o; o.x = v0 + bv.x; o.y = v1 + bv.y;
                    *(float2*)(Out + (size_t)rr * 512 + cg) = o;
                }
            }
        }
    }
}

// ===========================================================================
// fp16 flash attention. Grid (8,8,8), 256 thr, 8 warps x 16 q-rows.
// kv tile 64, 3-stage cp.async pipeline, ONE syncthreads per tile.
// ===========================================================================
#define AKP 80
#define ASTG_B (128 * AKP * 2)               // K(64)+V(64) = 20480 B per stage
#define ATT_SMEM (3 * ASTG_B)                // 61440 B

__global__ __launch_bounds__(256, 2) void attn_mma(const float* __restrict__ bias) {
    extern __shared__ __half smh[];
    const uint32_t sbase = smem_u32(smh);
    const int qt = blockIdx.x, h = blockIdx.y, b = blockIdx.z;
    const int tid = threadIdx.x, wid = tid >> 5, lane = tid & 31;
    const int g = lane >> 2, th = lane & 3;

    const size_t bh = (size_t)(b * NH + h);
    const __half* Kg = g_k + bh * NSEQ * HD;
    const __half* Vg = g_vt + bh * HD * NSEQ;

    const int qrow = qt * 128 + wid * 16 + g;
    const __half* Q0 = g_q + (bh * NSEQ + qrow) * HD;
    const __half* Q1 = Q0 + 8 * HD;
    uint32_t qa[4][4];
#pragma unroll
    for (int s = 0; s < 4; s++) {
        uint2 lo = *(const uint2*)(Q0 + 16 * s + 4 * th);
        uint2 hi = *(const uint2*)(Q1 + 16 * s + 4 * th);
        qa[s][0] = lo.x; qa[s][1] = hi.x; qa[s][2] = lo.y; qa[s][3] = hi.y;
    }

    int offK[8], offV[8];
#pragma unroll
    for (int na = 0; na < 8; na++) {
        offK[na] = (na * 8 + g) * AKP + 4 * th;
        offV[na] = 64 * AKP + (na * 8 + g) * AKP + 4 * th;
    }

    float O[8][4];
#pragma unroll
    for (int na = 0; na < 8; na++)
#pragma unroll
        for (int q = 0; q < 4; q++) O[na][q] = 0.0f;
    float mrow[2] = {-INFINITY, -INFINITY};
    float lrow[2] = {0.0f, 0.0f};

    const int arow = tid >> 2, aq = tid & 3;

#define A_ISSUE(T, ST)                                                        \
    {                                                                         \
        uint32_t _sb = sbase + (uint32_t)(ST) * ASTG_B;                       \
        uint32_t _kd = _sb + (arow * AKP) * 2 + aq * 32;                      \
        uint32_t _vd = _kd + 64 * AKP * 2;                                    \
        const __half* _ks = Kg + ((size_t)((T) * 64 + arow)) * 64 + aq * 16;  \
        const __half* _vs = Vg + (size_t)arow * NSEQ + (T) * 64 + aq * 16;    \
        CP16(_kd, _ks); CP16(_kd + 16, _ks + 8);                              \
        CP16(_vd, _vs); CP16(_vd + 16, _vs + 8);                              \
        CPCOMMIT();                                                           \
    }

    A_ISSUE(0, 0);
    A_ISSUE(1, 1);

    int st = 0, stn = 2;
    for (int t = 0; t < 16; t++) {
        if (t < 15) CPWAIT1(); else CPWAIT0();
        __syncthreads();
        if (t + 2 < 16) A_ISSUE(t + 2, stn);
        const __half* Ks = smh + st * (ASTG_B / 2);

        // S = Q K^T
        float S[8][4];
#pragma unroll
        for (int na = 0; na < 8; na++)
#pragma unroll
            for (int q = 0; q < 4; q++) S[na][q] = 0.0f;
#pragma unroll
        for (int s = 0; s < 4; s++) {
#pragma unroll
            for (int na = 0; na < 8; na++) {
                uint2 bv = *(const uint2*)(Ks + offK[na] + 16 * s);
                mma16(S[na], qa[s], bv.x, bv.y);
            }
        }

        // + bias (direct LDG)
        const float* bp0 = bias + ((size_t)h * NSEQ + qrow) * NSEQ + t * 64 + 2 * th;
        const float* bp1 = bp0 + 8 * NSEQ;
#pragma unroll
        for (int na = 0; na < 8; na++) {
            float2 b0v = *(const float2*)(bp0 + na * 8);
            float2 b1v = *(const float2*)(bp1 + na * 8);
            S[na][0] += b0v.x; S[na][1] += b0v.y;
            S[na][2] += b1v.x; S[na][3] += b1v.y;
        }

        // online softmax
#pragma unroll
        for (int e = 0; e < 2; e++) {
            float mx = -INFINITY;
#pragma unroll
            for (int na = 0; na < 8; na++)
                mx = fmaxf(mx, fmaxf(S[na][2 * e], S[na][2 * e + 1]));
            mx = fmaxf(mx, __shfl_xor_sync(0xffffffffu, mx, 1));
            mx = fmaxf(mx, __shfl_xor_sync(0xffffffffu, mx, 2));
            float mn = fmaxf(mrow[e], mx);
            float al = __expf(mrow[e] - mn);
            mrow[e] = mn;
            float ls = 0.0f;
#pragma unroll
            for (int na = 0; na < 8; na++) {
                S[na][2 * e]     = __expf(S[na][2 * e] - mn);
                S[na][2 * e + 1] = __expf(S[na][2 * e + 1] - mn);
                ls += S[na][2 * e] + S[na][2 * e + 1];
            }
            ls += __shfl_xor_sync(0xffffffffu, ls, 1);
            ls += __shfl_xor_sync(0xffffffffu, ls, 2);
            lrow[e] = lrow[e] * al + ls;
#pragma unroll
            for (int na = 0; na < 8; na++) { O[na][2 * e] *= al; O[na][2 * e + 1] *= al; }
        }

        // O += P V : A-frags = direct repack of own S regs
#pragma unroll
        for (int s = 0; s < 4; s++) {
            uint32_t a[4];
            a[0] = packh(S[2 * s][0],     S[2 * s][1]);
            a[1] = packh(S[2 * s][2],     S[2 * s][3]);
            a[2] = packh(S[2 * s + 1][0], S[2 * s + 1][1]);
            a[3] = packh(S[2 * s + 1][2], S[2 * s + 1][3]);
#pragma unroll
            for (int na = 0; na < 8; na++) {
                uint2 bv = *(const uint2*)(Ks + offV[na] + 16 * s);
                mma16(O[na], a, bv.x, bv.y);
            }
        }
        st = (st + 1 == 3) ? 0 : st + 1;
        stn = (stn + 1 == 3) ? 0 : stn + 1;
    }

    // normalize + write g_attnp (fp16 permuted)
    const float i0 = 1.0f / lrow[0];
    const float i1 = 1.0f / lrow[1];
    __half* ob0 = g_attnp + ((size_t)b * NSEQ + qrow) * DIMC;
    __half* ob1 = ob0 + (size_t)8 * DIMC;
#pragma unroll
    for (int na = 0; na < 8; na++) {
        int c = h * 64 + na * 8 + 2 * th;
        int cp = (c & ~15) + perm16(c & 15);
        *(__half2*)(ob0 + cp) = __floats2half2_rn(O[na][0] * i0, O[na][1] * i0);
        *(__half2*)(ob1 + cp) = __floats2half2_rn(O[na][2] * i1, O[na][3] * i1);
    }
}

extern "C" void kernel_launch(void* const* d_in, const int* in_sizes, int n_in,
                              void* d_out, int out_size) {
    const float* x      = (const float*)d_in[0];
    const float* rpe    = (const float*)d_in[1];
    const float* qkv_w  = (const float*)d_in[2];
    const float* proj_w = (const float*)d_in[3];
    const float* proj_b = (const float*)d_in[4];
    float* out = (float*)d_out;

    preperm<<<(10240 * 32 + 255) / 256, 256>>>(x, qkv_w, proj_w);
    cudaFuncSetAttribute(mma_gemm, cudaFuncAttributeMaxDynamicSharedMemorySize, GEMM_SMEM);
    cudaFuncSetAttribute(attn_mma, cudaFuncAttributeMaxDynamicSharedMemorySize, ATT_SMEM);
    mma_gemm<<<dim3(64, 12), 256, GEMM_SMEM>>>(nullptr, nullptr, 0);
    attn_mma<<<dim3(8, 8, 8), 256, ATT_SMEM>>>(rpe);
    mma_gemm<<<dim3(64, 4), 256, GEMM_SMEM>>>(proj_b, out, 1);
}

// round 13
// speedup vs baseline: 1.0098x; 1.0098x over previous
#include <cuda_runtime.h>
#include <cuda_fp16.h>
#include <cstdint>
#include <math.h>

#define DIMC  512
#define NH    8
#define HD    64
#define NB    8
#define NSEQ  1024
#define QK_SCALE 0.125f

// fp16 scratch, pair-permuted per 16-block: [0,1,8,9,2,3,10,11,4,5,12,13,6,7,14,15]
__device__ __half g_q[NB * NH * NSEQ * HD];      // [bh][n][d]  perm, *0.125
__device__ __half g_k[NB * NH * NSEQ * HD];      // [bh][n][d]  perm
__device__ __half g_vt[NB * NH * HD * NSEQ];     // [bh][d][kv] perm over kv
__device__ __half g_attnp[NB * NSEQ * DIMC];     // [b*n][c]    perm
__device__ __half g_xp[NB * NSEQ * DIMC];
__device__ __half g_wqkvp[3 * DIMC * DIMC];
__device__ __half g_wprojp[DIMC * DIMC];

__device__ __forceinline__ int perm16(int d) {
    return (((d & 7) >> 1) << 2) + (((d >> 3) & 1) << 1) + (d & 1);
}
__device__ __forceinline__ int perm16inv(int j) {
    return (((j >> 1) & 1) << 3) | (((j >> 3) & 1) << 2) | (((j >> 2) & 1) << 1) | (j & 1);
}
__device__ __forceinline__ uint32_t packh(float lo, float hi) {
    __half2 h = __floats2half2_rn(lo, hi);
    return *(uint32_t*)&h;
}
__device__ __forceinline__ void mma16(float* d, const uint32_t* a, uint32_t b0, uint32_t b1) {
    asm volatile(
        "mma.sync.aligned.m16n8k16.row.col.f32.f16.f16.f32 "
        "{%0,%1,%2,%3}, {%4,%5,%6,%7}, {%8,%9}, {%0,%1,%2,%3};"
        : "+f"(d[0]), "+f"(d[1]), "+f"(d[2]), "+f"(d[3])
        : "r"(a[0]), "r"(a[1]), "r"(a[2]), "r"(a[3]), "r"(b0), "r"(b1));
}
__device__ __forceinline__ uint32_t smem_u32(const void* p) {
    uint32_t a;
    asm("{ .reg .u64 t; cvta.to.shared.u64 t, %1; cvt.u32.u64 %0, t; }" : "=r"(a) : "l"(p));
    return a;
}
#define CP16(d, s) asm volatile("cp.async.cg.shared.global [%0], [%1], 16;" :: "r"(d), "l"(s))
#define CPCOMMIT() asm volatile("cp.async.commit_group;" ::: "memory")
#define CPWAIT1()  asm volatile("cp.async.wait_group 1;" ::: "memory")
#define CPWAIT0()  asm volatile("cp.async.wait_group 0;" ::: "memory")

// ===========================================================================
// Pre-pass: fp32 -> fp16 permuted.
// ===========================================================================
__global__ __launch_bounds__(256) void preperm(const float* __restrict__ x,
                                               const float* __restrict__ wq,
                                               const float* __restrict__ wp) {
    int idx = blockIdx.x * 256 + threadIdx.x;
    if (idx >= 10240 * 32) return;
    int row = idx >> 5, blk = idx & 31;
    const float* src; __half* dst; int r;
    if (row < 8192)      { r = row;        src = x  + (size_t)r * 512; dst = g_xp    + (size_t)r * 512; }
    else if (row < 9728) { r = row - 8192; src = wq + (size_t)r * 512; dst = g_wqkvp + (size_t)r * 512; }
    else                 { r = row - 9728; src = wp + (size_t)r * 512; dst = g_wprojp + (size_t)r * 512; }
    float f[16];
    const float4* s4 = (const float4*)(src + blk * 16);
#pragma unroll
    for (int i = 0; i < 4; i++) { float4 v = s4[i]; f[4*i] = v.x; f[4*i+1] = v.y; f[4*i+2] = v.z; f[4*i+3] = v.w; }
    uint32_t u[8];
#pragma unroll
    for (int k = 0; k < 8; k++) {
        int e = 2 * (k >> 1) + 8 * (k & 1);
        u[k] = packh(f[e], f[e + 1]);
    }
    uint4* d4 = (uint4*)(dst + blk * 16);
    d4[0] = make_uint4(u[0], u[1], u[2], u[3]);
    d4[1] = make_uint4(u[4], u[5], u[6], u[7]);
}

// ===========================================================================
// fp16 GEMM: CTA 128x128, 256 thr, 8 warps (2x4), warp tile 64x32,
// BK=64 halfs (8 iterations), 2-stage cp.async, pitch 80 halfs.
// mode 0: y-tile 0-3 -> q, 4-7 -> k (direct), 8-11 -> V (smem-staged coalesced)
// mode 1: +bias, f32 Out
// ===========================================================================
#define GP 80
#define GSTAGE_B (256 * GP * 2)              // 40960 B per stage
#define GEMM_SMEM (2 * GSTAGE_B)             // 81920 B
#define SVP 136                              // V staging pitch (halfs)

__global__ __launch_bounds__(256, 2) void mma_gemm(const float* __restrict__ Bvec,
                                                   float* __restrict__ Out,
                                                   int mode) {
    extern __shared__ __half smh[];
    const uint32_t sbase = smem_u32(smh);
    const int tid = threadIdx.x, wid = tid >> 5, lane = tid & 31;
    const int g = lane >> 2, th = lane & 3;
    const int wm = wid >> 2, wn = wid & 3;
    const int bm = blockIdx.x * 128, bn = blockIdx.y * 128;

    const __half* Ap = mode ? g_attnp : g_xp;
    const __half* Wp = mode ? g_wprojp : g_wqkvp;
    const int lrow = tid & 127, side = tid >> 7;
    const __half* gsrc = side ? (Wp + (size_t)(bn + lrow) * 512)
                              : (Ap + (size_t)(bm + lrow) * 512);
    const uint32_t dst0 = sbase + (uint32_t)((side * 128 + lrow) * GP) * 2;

    int offA0[4], offA1[4], offB[4];
#pragma unroll
    for (int ma = 0; ma < 4; ma++) {
        int ra = wm * 64 + ma * 16 + g;
        offA0[ma] = ra * GP + 4 * th;
        offA1[ma] = (ra + 8) * GP + 4 * th;
    }
#pragma unroll
    for (int nb = 0; nb < 4; nb++)
        offB[nb] = 128 * GP + (wn * 32 + nb * 8 + g) * GP + 4 * th;

    float acc[4][4][4];
#pragma unroll
    for (int i = 0; i < 4; i++)
#pragma unroll
        for (int j = 0; j < 4; j++)
#pragma unroll
            for (int q = 0; q < 4; q++) acc[i][j][q] = 0.0f;

#define G_ISSUE(I)                                                        \
    {                                                                     \
        uint32_t _d = dst0 + ((I) & 1) * GSTAGE_B;                        \
        const __half* _s = gsrc + (I) * 64;                               \
        _Pragma("unroll")                                                 \
        for (int c = 0; c < 8; c++) CP16(_d + c * 16, _s + c * 8);        \
        CPCOMMIT();                                                       \
    }

    G_ISSUE(0);
    G_ISSUE(1);

    for (int i = 0; i < 8; i++) {
        if (i < 7) CPWAIT1(); else CPWAIT0();
        __syncthreads();
        const __half* S0 = smh + (i & 1) * (GSTAGE_B / 2);
#pragma unroll
        for (int s = 0; s < 4; s++) {
            uint32_t Af[4][4];
#pragma unroll
            for (int ma = 0; ma < 4; ma++) {
                uint2 lo = *(const uint2*)(S0 + offA0[ma] + 16 * s);
                uint2 hi = *(const uint2*)(S0 + offA1[ma] + 16 * s);
                Af[ma][0] = lo.x; Af[ma][1] = hi.x; Af[ma][2] = lo.y; Af[ma][3] = hi.y;
            }
#pragma unroll
            for (int nb = 0; nb < 4; nb++) {
                uint2 bv = *(const uint2*)(S0 + offB[nb] + 16 * s);
#pragma unroll
                for (int ma = 0; ma < 4; ma++) mma16(acc[ma][nb], Af[ma], bv.x, bv.y);
            }
        }
        __syncthreads();
        if (i + 2 < 8) G_ISSUE(i + 2);
    }

    if (mode == 0) {
        const int which = blockIdx.y >> 2;            // 0:q 1:k 2:v
        if (which == 2) {
            // ---- V: stage tile transposed in smem, then coalesced STG ----
            __half* SV = smh;                          // [128 dd][SVP]
#pragma unroll
            for (int ma = 0; ma < 4; ma++) {
#pragma unroll
                for (int nb = 0; nb < 4; nb++) {
                    int col = wn * 32 + nb * 8 + 2 * th;
#pragma unroll
                    for (int e = 0; e < 2; e++) {
                        int m = wm * 64 + ma * 16 + g + e * 8;
                        SV[(col)     * SVP + m] = __float2half_rn(acc[ma][nb][2 * e]);
                        SV[(col + 1) * SVP + m] = __float2half_rn(acc[ma][nb][2 * e + 1]);
                    }
                }
            }
            __syncthreads();
            const int bb = bm >> 10, n0 = bm & 1023;
#pragma unroll
            for (int p = 0; p < 4; p++) {
                int seg = tid + p * 256;
                int dl = seg >> 3, blk = seg & 7;
                int cg = bn + dl;
                int hh = (cg >> 6) & 7, dd = cg & 63;
                size_t bh2 = (size_t)(bb * NH + hh);
                const __half* row = SV + dl * SVP + blk * 16;
                uint32_t u[8];
#pragma unroll
                for (int i2 = 0; i2 < 8; i2++) {
                    __half2 hv = __halves2half2(row[perm16inv(2 * i2)],
                                                row[perm16inv(2 * i2 + 1)]);
                    u[i2] = *(uint32_t*)&hv;
                }
                uint4* dst = (uint4*)(g_vt + (bh2 * HD + dd) * NSEQ + n0 + blk * 16);
                dst[0] = make_uint4(u[0], u[1], u[2], u[3]);
                dst[1] = make_uint4(u[4], u[5], u[6], u[7]);
            }
        } else {
            // ---- q / k: direct half2 stores (perm within 16-blocks) ----
            __half* base = which ? g_k : g_q;
            const float sc = which ? 1.0f : QK_SCALE;
#pragma unroll
            for (int ma = 0; ma < 4; ma++) {
#pragma unroll
                for (int nb = 0; nb < 4; nb++) {
                    int r0 = bm + wm * 64 + ma * 16 + g;
                    int cg = bn + wn * 32 + nb * 8 + 2 * th;
                    int hh = (cg >> 6) & 7, dd = cg & 63;
#pragma unroll
                    for (int e = 0; e < 2; e++) {
                        int rr = r0 + e * 8;
                        int bb = rr >> 10, n = rr & 1023;
                        size_t off = (((size_t)(bb * NH + hh)) * NSEQ + n) * HD
                                   + (dd & ~15) + perm16(dd & 15);
                        *(__half2*)(base + off) =
                            __floats2half2_rn(acc[ma][nb][2 * e] * sc,
                                              acc[ma][nb][2 * e + 1] * sc);
                    }
                }
            }
        }
    } else {
#pragma unroll
        for (int ma = 0; ma < 4; ma++) {
#pragma unroll
            for (int nb = 0; nb < 4; nb++) {
                int r0 = bm + wm * 64 + ma * 16 + g;
                int cg = bn + wn * 32 + nb * 8 + 2 * th;
                float2 bv = *(const float2*)(Bvec + cg);
#pragma unroll
                for (int e = 0; e < 2; e++) {
                    int rr = r0 + e * 8;
                    float2 o;
                    o.x = acc[ma][nb][2 * e] + bv.x;
                    o.y = acc[ma][nb][2 * e + 1] + bv.y;
                    *(float2*)(Out + (size_t)rr * 512 + cg) = o;
                }
            }
        }
    }
}

// ===========================================================================
// fp16 flash attention (R10 known-best). Grid (8,8,8), 256 thr, 8 warps.
// 2-stage cp.async, kv tile 64, PV A-frags = direct repack of S regs.
// ===========================================================================
#define AKP 80
#define ASTG_B (128 * AKP * 2)               // 20480 B per stage
#define ATT_SMEM (2 * ASTG_B)                // 40960 B

__global__ __launch_bounds__(256) void attn_mma(const float* __restrict__ bias) {
    extern __shared__ __half smh[];
    const uint32_t sbase = smem_u32(smh);
    const int qt = blockIdx.x, h = blockIdx.y, b = blockIdx.z;
    const int tid = threadIdx.x, wid = tid >> 5, lane = tid & 31;
    const int g = lane >> 2, th = lane & 3;

    const size_t bh = (size_t)(b * NH + h);
    const __half* Kg = g_k + bh * NSEQ * HD;
    const __half* Vg = g_vt + bh * HD * NSEQ;

    const int qrow = qt * 128 + wid * 16 + g;
    const __half* Q0 = g_q + (bh * NSEQ + qrow) * HD;
    const __half* Q1 = Q0 + 8 * HD;
    uint32_t qa[4][4];
#pragma unroll
    for (int s = 0; s < 4; s++) {
        uint2 lo = *(const uint2*)(Q0 + 16 * s + 4 * th);
        uint2 hi = *(const uint2*)(Q1 + 16 * s + 4 * th);
        qa[s][0] = lo.x; qa[s][1] = hi.x; qa[s][2] = lo.y; qa[s][3] = hi.y;
    }

    int offK[8], offV[8];
#pragma unroll
    for (int na = 0; na < 8; na++) {
        offK[na] = (na * 8 + g) * AKP + 4 * th;
        offV[na] = 64 * AKP + (na * 8 + g) * AKP + 4 * th;
    }

    float O[8][4];
#pragma unroll
    for (int na = 0; na < 8; na++)
#pragma unroll
        for (int q = 0; q < 4; q++) O[na][q] = 0.0f;
    float mrow[2] = {-INFINITY, -INFINITY};
    float lrow[2] = {0.0f, 0.0f};

    const int arow = tid >> 2, aq = tid & 3;

#define A_ISSUE(T)                                                            \
    {                                                                         \
        uint32_t _sb = sbase + ((T) & 1) * ASTG_B;                            \
        uint32_t _kd = _sb + (arow * AKP) * 2 + aq * 32;                      \
        uint32_t _vd = _kd + 64 * AKP * 2;                                    \
        const __half* _ks = Kg + ((size_t)((T) * 64 + arow)) * 64 + aq * 16;  \
        const __half* _vs = Vg + (size_t)arow * NSEQ + (T) * 64 + aq * 16;    \
        CP16(_kd, _ks); CP16(_kd + 16, _ks + 8);                              \
        CP16(_vd, _vs); CP16(_vd + 16, _vs + 8);                              \
        CPCOMMIT();                                                           \
    }

    A_ISSUE(0);

    for (int t = 0; t < 16; t++) {
        if (t < 15) { A_ISSUE(t + 1); CPWAIT1(); } else { CPWAIT0(); }
        __syncthreads();
        const __half* Ks = smh + (t & 1) * (ASTG_B / 2);

        float S[8][4];
#pragma unroll
        for (int na = 0; na < 8; na++)
#pragma unroll
            for (int q = 0; q < 4; q++) S[na][q] = 0.0f;
#pragma unroll
        for (int s = 0; s < 4; s++) {
#pragma unroll
            for (int na = 0; na < 8; na++) {
                uint2 bv = *(const uint2*)(Ks + offK[na] + 16 * s);
                mma16(S[na], qa[s], bv.x, bv.y);
            }
        }

        const float* bp0 = bias + ((size_t)h * NSEQ + qrow) * NSEQ + t * 64 + 2 * th;
        const float* bp1 = bp0 + 8 * NSEQ;
#pragma unroll
        for (int na = 0; na < 8; na++) {
            float2 b0v = *(const float2*)(bp0 + na * 8);
            float2 b1v = *(const float2*)(bp1 + na * 8);
            S[na][0] += b0v.x; S[na][1] += b0v.y;
            S[na][2] += b1v.x; S[na][3] += b1v.y;
        }

#pragma unroll
        for (int e = 0; e < 2; e++) {
            float mx = -INFINITY;
#pragma unroll
            for (int na = 0; na < 8; na++)
                mx = fmaxf(mx, fmaxf(S[na][2 * e], S[na][2 * e + 1]));
            mx = fmaxf(mx, __shfl_xor_sync(0xffffffffu, mx, 1));
            mx = fmaxf(mx, __shfl_xor_sync(0xffffffffu, mx, 2));
            float mn = fmaxf(mrow[e], mx);
            float al = __expf(mrow[e] - mn);
            mrow[e] = mn;
            float ls = 0.0f;
#pragma unroll
            for (int na = 0; na < 8; na++) {
                S[na][2 * e]     = __expf(S[na][2 * e] - mn);
                S[na][2 * e + 1] = __expf(S[na][2 * e + 1] - mn);
                ls += S[na][2 * e] + S[na][2 * e + 1];
            }
            ls += __shfl_xor_sync(0xffffffffu, ls, 1);
            ls += __shfl_xor_sync(0xffffffffu, ls, 2);
            lrow[e] = lrow[e] * al + ls;
#pragma unroll
            for (int na = 0; na < 8; na++) { O[na][2 * e] *= al; O[na][2 * e + 1] *= al; }
        }

#pragma unroll
        for (int s = 0; s < 4; s++) {
            uint32_t a[4];
            a[0] = packh(S[2 * s][0],     S[2 * s][1]);
            a[1] = packh(S[2 * s][2],     S[2 * s][3]);
            a[2] = packh(S[2 * s + 1][0], S[2 * s + 1][1]);
            a[3] = packh(S[2 * s + 1][2], S[2 * s + 1][3]);
#pragma unroll
            for (int na = 0; na < 8; na++) {
                uint2 bv = *(const uint2*)(Ks + offV[na] + 16 * s);
                mma16(O[na], a, bv.x, bv.y);
            }
        }
        __syncthreads();
    }

    const float i0 = 1.0f / lrow[0];
    const float i1 = 1.0f / lrow[1];
    __half* ob0 = g_attnp + ((size_t)b * NSEQ + qrow) * DIMC;
    __half* ob1 = ob0 + (size_t)8 * DIMC;
#pragma unroll
    for (int na = 0; na < 8; na++) {
        int c = h * 64 + na * 8 + 2 * th;
        int cp = (c & ~15) + perm16(c & 15);
        *(__half2*)(ob0 + cp) = __floats2half2_rn(O[na][0] * i0, O[na][1] * i0);
        *(__half2*)(ob1 + cp) = __floats2half2_rn(O[na][2] * i1, O[na][3] * i1);
    }
}

extern "C" void kernel_launch(void* const* d_in, const int* in_sizes, int n_in,
                              void* d_out, int out_size) {
    const float* x      = (const float*)d_in[0];
    const float* rpe    = (const float*)d_in[1];
    const float* qkv_w  = (const float*)d_in[2];
    const float* proj_w = (const float*)d_in[3];
    const float* proj_b = (const float*)d_in[4];
    float* out = (float*)d_out;

    preperm<<<(10240 * 32 + 255) / 256, 256>>>(x, qkv_w, proj_w);
    cudaFuncSetAttribute(mma_gemm, cudaFuncAttributeMaxDynamicSharedMemorySize, GEMM_SMEM);
    mma_gemm<<<dim3(64, 12), 256, GEMM_SMEM>>>(nullptr, nullptr, 0);
    attn_mma<<<dim3(8, 8, 8), 256, ATT_SMEM>>>(rpe);
    mma_gemm<<<dim3(64, 4), 256, GEMM_SMEM>>>(proj_b, out, 1);
}

// round 14
// speedup vs baseline: 1.0186x; 1.0088x over previous
#include <cuda_runtime.h>
#include <cuda_fp16.h>
#include <cstdint>
#include <math.h>

#define DIMC  512
#define NH    8
#define HD    64
#define NB    8
#define NSEQ  1024
#define QK_SCALE 0.125f

// fp16 scratch, pair-permuted per 16-block
__device__ __half g_q[NB * NH * NSEQ * HD];
__device__ __half g_k[NB * NH * NSEQ * HD];
__device__ __half g_vt[NB * NH * HD * NSEQ];
__device__ __half g_attnp[NB * NSEQ * DIMC];
__device__ __half g_xp[NB * NSEQ * DIMC];
__device__ __half g_wqkvp[3 * DIMC * DIMC];
__device__ __half g_wprojp[DIMC * DIMC];

__device__ __forceinline__ int perm16(int d) {
    return (((d & 7) >> 1) << 2) + (((d >> 3) & 1) << 1) + (d & 1);
}
__device__ __forceinline__ int perm16inv(int j) {
    return (((j >> 1) & 1) << 3) | (((j >> 3) & 1) << 2) | (((j >> 2) & 1) << 1) | (j & 1);
}
__device__ __forceinline__ uint32_t packh(float lo, float hi) {
    __half2 h = __floats2half2_rn(lo, hi);
    return *(uint32_t*)&h;
}
__device__ __forceinline__ void mma16(float* d, const uint32_t* a, uint32_t b0, uint32_t b1) {
    asm volatile(
        "mma.sync.aligned.m16n8k16.row.col.f32.f16.f16.f32 "
        "{%0,%1,%2,%3}, {%4,%5,%6,%7}, {%8,%9}, {%0,%1,%2,%3};"
        : "+f"(d[0]), "+f"(d[1]), "+f"(d[2]), "+f"(d[3])
        : "r"(a[0]), "r"(a[1]), "r"(a[2]), "r"(a[3]), "r"(b0), "r"(b1));
}
__device__ __forceinline__ uint32_t smem_u32(const void* p) {
    uint32_t a;
    asm("{ .reg .u64 t; cvta.to.shared.u64 t, %1; cvt.u32.u64 %0, t; }" : "=r"(a) : "l"(p));
    return a;
}
#define CP16(d, s) asm volatile("cp.async.cg.shared.global [%0], [%1], 16;" :: "r"(d), "l"(s))
#define CPCOMMIT() asm volatile("cp.async.commit_group;" ::: "memory")
#define CPWAIT1()  asm volatile("cp.async.wait_group 1;" ::: "memory")
#define CPWAIT0()  asm volatile("cp.async.wait_group 0;" ::: "memory")

// ===========================================================================
// Pre-pass: fp32 -> fp16 permuted.
// ===========================================================================
__global__ __launch_bounds__(256) void preperm(const float* __restrict__ x,
                                               const float* __restrict__ wq,
                                               const float* __restrict__ wp) {
    int idx = blockIdx.x * 256 + threadIdx.x;
    if (idx >= 10240 * 32) return;
    int row = idx >> 5, blk = idx & 31;
    const float* src; __half* dst; int r;
    if (row < 8192)      { r = row;        src = x  + (size_t)r * 512; dst = g_xp    + (size_t)r * 512; }
    else if (row < 9728) { r = row - 8192; src = wq + (size_t)r * 512; dst = g_wqkvp + (size_t)r * 512; }
    else                 { r = row - 9728; src = wp + (size_t)r * 512; dst = g_wprojp + (size_t)r * 512; }
    float f[16];
    const float4* s4 = (const float4*)(src + blk * 16);
#pragma unroll
    for (int i = 0; i < 4; i++) { float4 v = s4[i]; f[4*i] = v.x; f[4*i+1] = v.y; f[4*i+2] = v.z; f[4*i+3] = v.w; }
    uint32_t u[8];
#pragma unroll
    for (int k = 0; k < 8; k++) {
        int e = 2 * (k >> 1) + 8 * (k & 1);
        u[k] = packh(f[e], f[e + 1]);
    }
    uint4* d4 = (uint4*)(dst + blk * 16);
    d4[0] = make_uint4(u[0], u[1], u[2], u[3]);
    d4[1] = make_uint4(u[4], u[5], u[6], u[7]);
}

// ===========================================================================
// fp16 GEMM: CTA 128x128, 256 thr, 8 warps (2x4), warp tile 64x32, BK=64,
// 2-stage cp.async, register-double-buffered fragments (prefetch s+1).
// ===========================================================================
#define GP 80
#define GSTAGE_B (256 * GP * 2)              // 40960 B per stage
#define GEMM_SMEM (2 * GSTAGE_B)             // 81920 B
#define SVP 136

__global__ __launch_bounds__(256) void mma_gemm(const float* __restrict__ Bvec,
                                                float* __restrict__ Out,
                                                int mode) {
    extern __shared__ __half smh[];
    const uint32_t sbase = smem_u32(smh);
    const int tid = threadIdx.x, wid = tid >> 5, lane = tid & 31;
    const int g = lane >> 2, th = lane & 3;
    const int wm = wid >> 2, wn = wid & 3;
    const int bm = blockIdx.x * 128, bn = blockIdx.y * 128;

    const __half* Ap = mode ? g_attnp : g_xp;
    const __half* Wp = mode ? g_wprojp : g_wqkvp;
    const int lrow = tid & 127, side = tid >> 7;
    const __half* gsrc = side ? (Wp + (size_t)(bn + lrow) * 512)
                              : (Ap + (size_t)(bm + lrow) * 512);
    const uint32_t dst0 = sbase + (uint32_t)((side * 128 + lrow) * GP) * 2;

    int offA0[4], offA1[4], offB[4];
#pragma unroll
    for (int ma = 0; ma < 4; ma++) {
        int ra = wm * 64 + ma * 16 + g;
        offA0[ma] = ra * GP + 4 * th;
        offA1[ma] = (ra + 8) * GP + 4 * th;
    }
#pragma unroll
    for (int nb = 0; nb < 4; nb++)
        offB[nb] = 128 * GP + (wn * 32 + nb * 8 + g) * GP + 4 * th;

    float acc[4][4][4];
#pragma unroll
    for (int i = 0; i < 4; i++)
#pragma unroll
        for (int j = 0; j < 4; j++)
#pragma unroll
            for (int q = 0; q < 4; q++) acc[i][j][q] = 0.0f;

#define G_ISSUE(I)                                                        \
    {                                                                     \
        uint32_t _d = dst0 + ((I) & 1) * GSTAGE_B;                        \
        const __half* _s = gsrc + (I) * 64;                               \
        _Pragma("unroll")                                                 \
        for (int c = 0; c < 8; c++) CP16(_d + c * 16, _s + c * 8);        \
        CPCOMMIT();                                                       \
    }

#define LOAD_FRAG(P, S0, S)                                               \
    {                                                                     \
        _Pragma("unroll")                                                 \
        for (int ma = 0; ma < 4; ma++) {                                  \
            uint2 lo = *(const uint2*)((S0) + offA0[ma] + 16 * (S));      \
            uint2 hi = *(const uint2*)((S0) + offA1[ma] + 16 * (S));      \
            Af[P][ma][0] = lo.x; Af[P][ma][1] = hi.x;                     \
            Af[P][ma][2] = lo.y; Af[P][ma][3] = hi.y;                     \
        }                                                                 \
        _Pragma("unroll")                                                 \
        for (int nb = 0; nb < 4; nb++)                                    \
            Bf[P][nb] = *(const uint2*)((S0) + offB[nb] + 16 * (S));      \
    }

    G_ISSUE(0);
    G_ISSUE(1);

    uint32_t Af[2][4][4];
    uint2 Bf[2][4];

    for (int i = 0; i < 8; i++) {
        if (i < 7) CPWAIT1(); else CPWAIT0();
        __syncthreads();
        const __half* S0 = smh + (i & 1) * (GSTAGE_B / 2);
        LOAD_FRAG(0, S0, 0);
#pragma unroll
        for (int s = 0; s < 4; s++) {
            if (s < 3) LOAD_FRAG((s + 1) & 1, S0, s + 1);
            const int p = s & 1;
#pragma unroll
            for (int nb = 0; nb < 4; nb++)
#pragma unroll
                for (int ma = 0; ma < 4; ma++)
                    mma16(acc[ma][nb], Af[p][ma], Bf[p][nb].x, Bf[p][nb].y);
        }
        __syncthreads();
        if (i + 2 < 8) G_ISSUE(i + 2);
    }

    if (mode == 0) {
        const int which = blockIdx.y >> 2;
        if (which == 2) {
            __half* SV = smh;
#pragma unroll
            for (int ma = 0; ma < 4; ma++)
#pragma unroll
                for (int nb = 0; nb < 4; nb++) {
                    int col = wn * 32 + nb * 8 + 2 * th;
#pragma unroll
                    for (int e = 0; e < 2; e++) {
                        int m = wm * 64 + ma * 16 + g + e * 8;
                        SV[(col)     * SVP + m] = __float2half_rn(acc[ma][nb][2 * e]);
                        SV[(col + 1) * SVP + m] = __float2half_rn(acc[ma][nb][2 * e + 1]);
                    }
                }
            __syncthreads();
            const int bb = bm >> 10, n0 = bm & 1023;
#pragma unroll
            for (int p = 0; p < 4; p++) {
                int seg = tid + p * 256;
                int dl = seg >> 3, blk = seg & 7;
                int cg = bn + dl;
                int hh = (cg >> 6) & 7, dd = cg & 63;
                size_t bh2 = (size_t)(bb * NH + hh);
                const __half* row = SV + dl * SVP + blk * 16;
                uint32_t u[8];
#pragma unroll
                for (int i2 = 0; i2 < 8; i2++) {
                    __half2 hv = __halves2half2(row[perm16inv(2 * i2)],
                                                row[perm16inv(2 * i2 + 1)]);
                    u[i2] = *(uint32_t*)&hv;
                }
                uint4* dst = (uint4*)(g_vt + (bh2 * HD + dd) * NSEQ + n0 + blk * 16);
                dst[0] = make_uint4(u[0], u[1], u[2], u[3]);
                dst[1] = make_uint4(u[4], u[5], u[6], u[7]);
            }
        } else {
            __half* base = which ? g_k : g_q;
            const float sc = which ? 1.0f : QK_SCALE;
#pragma unroll
            for (int ma = 0; ma < 4; ma++)
#pragma unroll
                for (int nb = 0; nb < 4; nb++) {
                    int r0 = bm + wm * 64 + ma * 16 + g;
                    int cg = bn + wn * 32 + nb * 8 + 2 * th;
                    int hh = (cg >> 6) & 7, dd = cg & 63;
#pragma unroll
                    for (int e = 0; e < 2; e++) {
                        int rr = r0 + e * 8;
                        int bb = rr >> 10, n = rr & 1023;
                        size_t off = (((size_t)(bb * NH + hh)) * NSEQ + n) * HD
                                   + (dd & ~15) + perm16(dd & 15);
                        *(__half2*)(base + off) =
                            __floats2half2_rn(acc[ma][nb][2 * e] * sc,
                                              acc[ma][nb][2 * e + 1] * sc);
                    }
                }
        }
    } else {
#pragma unroll
        for (int ma = 0; ma < 4; ma++)
#pragma unroll
            for (int nb = 0; nb < 4; nb++) {
                int r0 = bm + wm * 64 + ma * 16 + g;
                int cg = bn + wn * 32 + nb * 8 + 2 * th;
                float2 bv = *(const float2*)(Bvec + cg);
#pragma unroll
                for (int e = 0; e < 2; e++) {
                    int rr = r0 + e * 8;
                    float2 o;
                    o.x = acc[ma][nb][2 * e] + bv.x;
                    o.y = acc[ma][nb][2 * e + 1] + bv.y;
                    *(float2*)(Out + (size_t)rr * 512 + cg) = o;
                }
            }
    }
}

// ===========================================================================
// fp16 flash attention, register-pipelined. Grid (8,8,8), 256 thr, 8 warps.
// Bias LDGs hoisted before QK MMAs; V frag s=0 loaded before softmax.
// ===========================================================================
#define AKP 80
#define ASTG_B (128 * AKP * 2)
#define ATT_SMEM (2 * ASTG_B)

__global__ __launch_bounds__(256) void attn_mma(const float* __restrict__ bias) {
    extern __shared__ __half smh[];
    const uint32_t sbase = smem_u32(smh);
    const int qt = blockIdx.x, h = blockIdx.y, b = blockIdx.z;
    const int tid = threadIdx.x, wid = tid >> 5, lane = tid & 31;
    const int g = lane >> 2, th = lane & 3;

    const size_t bh = (size_t)(b * NH + h);
    const __half* Kg = g_k + bh * NSEQ * HD;
    const __half* Vg = g_vt + bh * HD * NSEQ;

    const int qrow = qt * 128 + wid * 16 + g;
    const __half* Q0 = g_q + (bh * NSEQ + qrow) * HD;
    const __half* Q1 = Q0 + 8 * HD;
    uint32_t qa[4][4];
#pragma unroll
    for (int s = 0; s < 4; s++) {
        uint2 lo = *(const uint2*)(Q0 + 16 * s + 4 * th);
        uint2 hi = *(const uint2*)(Q1 + 16 * s + 4 * th);
        qa[s][0] = lo.x; qa[s][1] = hi.x; qa[s][2] = lo.y; qa[s][3] = hi.y;
    }

    int offK[8], offV[8];
#pragma unroll
    for (int na = 0; na < 8; na++) {
        offK[na] = (na * 8 + g) * AKP + 4 * th;
        offV[na] = 64 * AKP + (na * 8 + g) * AKP + 4 * th;
    }

    float O[8][4];
#pragma unroll
    for (int na = 0; na < 8; na++)
#pragma unroll
        for (int q = 0; q < 4; q++) O[na][q] = 0.0f;
    float mrow[2] = {-INFINITY, -INFINITY};
    float lrow[2] = {0.0f, 0.0f};

    const int arow = tid >> 2, aq = tid & 3;

#define A_ISSUE(T)                                                            \
    {                                                                         \
        uint32_t _sb = sbase + ((T) & 1) * ASTG_B;                            \
        uint32_t _kd = _sb + (arow * AKP) * 2 + aq * 32;                      \
        uint32_t _vd = _kd + 64 * AKP * 2;                                    \
        const __half* _ks = Kg + ((size_t)((T) * 64 + arow)) * 64 + aq * 16;  \
        const __half* _vs = Vg + (size_t)arow * NSEQ + (T) * 64 + aq * 16;    \
        CP16(_kd, _ks); CP16(_kd + 16, _ks + 8);                              \
        CP16(_vd, _vs); CP16(_vd + 16, _vs + 8);                              \
        CPCOMMIT();                                                           \
    }

#define LOAD_KF(P, S)                                                         \
    {                                                                         \
        _Pragma("unroll")                                                     \
        for (int na = 0; na < 8; na++)                                        \
            Kf[P][na] = *(const uint2*)(Ks + offK[na] + 16 * (S));            \
    }
#define LOAD_VF(P, S)                                                         \
    {                                                                         \
        _Pragma("unroll")                                                     \
        for (int na = 0; na < 8; na++)                                        \
            Vf[P][na] = *(const uint2*)(Ks + offV[na] + 16 * (S));            \
    }

    A_ISSUE(0);

    uint2 Kf[2][8], Vf[2][8];

    for (int t = 0; t < 16; t++) {
        if (t < 15) { A_ISSUE(t + 1); CPWAIT1(); } else { CPWAIT0(); }
        __syncthreads();
        const __half* Ks = smh + (t & 1) * (ASTG_B / 2);

        // hoisted bias loads (independent of K tile) — fly during QK MMAs
        const float* bp0 = bias + ((size_t)h * NSEQ + qrow) * NSEQ + t * 64 + 2 * th;
        const float* bp1 = bp0 + 8 * NSEQ;
        float2 bv0[8], bv1[8];
#pragma unroll
        for (int na = 0; na < 8; na++) {
            bv0[na] = *(const float2*)(bp0 + na * 8);
            bv1[na] = *(const float2*)(bp1 + na * 8);
        }

        // S = Q K^T, fragment-pipelined
        float S[8][4];
#pragma unroll
        for (int na = 0; na < 8; na++)
#pragma unroll
            for (int q = 0; q < 4; q++) S[na][q] = 0.0f;
        LOAD_KF(0, 0);
#pragma unroll
        for (int s = 0; s < 4; s++) {
            if (s < 3) LOAD_KF((s + 1) & 1, s + 1);
            const int p = s & 1;
#pragma unroll
            for (int na = 0; na < 8; na++)
                mma16(S[na], qa[s], Kf[p][na].x, Kf[p][na].y);
        }

#pragma unroll
        for (int na = 0; na < 8; na++) {
            S[na][0] += bv0[na].x; S[na][1] += bv0[na].y;
            S[na][2] += bv1[na].x; S[na][3] += bv1[na].y;
        }

        // V frag s=0 loads hide under softmax
        LOAD_VF(0, 0);

        // online softmax
#pragma unroll
        for (int e = 0; e < 2; e++) {
            float mx = -INFINITY;
#pragma unroll
            for (int na = 0; na < 8; na++)
                mx = fmaxf(mx, fmaxf(S[na][2 * e], S[na][2 * e + 1]));
            mx = fmaxf(mx, __shfl_xor_sync(0xffffffffu, mx, 1));
            mx = fmaxf(mx, __shfl_xor_sync(0xffffffffu, mx, 2));
            float mn = fmaxf(mrow[e], mx);
            float al = __expf(mrow[e] - mn);
            mrow[e] = mn;
            float ls = 0.0f;
#pragma unroll
            for (int na = 0; na < 8; na++) {
                S[na][2 * e]     = __expf(S[na][2 * e] - mn);
                S[na][2 * e + 1] = __expf(S[na][2 * e + 1] - mn);
                ls += S[na][2 * e] + S[na][2 * e + 1];
            }
            ls += __shfl_xor_sync(0xffffffffu, ls, 1);
            ls += __shfl_xor_sync(0xffffffffu, ls, 2);
            lrow[e] = lrow[e] * al + ls;
#pragma unroll
            for (int na = 0; na < 8; na++) { O[na][2 * e] *= al; O[na][2 * e + 1] *= al; }
        }

        // O += P V, fragment-pipelined; A-frags = repack of own S regs
#pragma unroll
        for (int s = 0; s < 4; s++) {
            if (s < 3) LOAD_VF((s + 1) & 1, s + 1);
            const int p = s & 1;
            uint32_t a[4];
            a[0] = packh(S[2 * s][0],     S[2 * s][1]);
            a[1] = packh(S[2 * s][2],     S[2 * s][3]);
            a[2] = packh(S[2 * s + 1][0], S[2 * s + 1][1]);
            a[3] = packh(S[2 * s + 1][2], S[2 * s + 1][3]);
#pragma unroll
            for (int na = 0; na < 8; na++)
                mma16(O[na], a, Vf[p][na].x, Vf[p][na].y);
        }
        __syncthreads();
    }

    const float i0 = 1.0f / lrow[0];
    const float i1 = 1.0f / lrow[1];
    __half* ob0 = g_attnp + ((size_t)b * NSEQ + qrow) * DIMC;
    __half* ob1 = ob0 + (size_t)8 * DIMC;
#pragma unroll
    for (int na = 0; na < 8; na++) {
        int c = h * 64 + na * 8 + 2 * th;
        int cp = (c & ~15) + perm16(c & 15);
        *(__half2*)(ob0 + cp) = __floats2half2_rn(O[na][0] * i0, O[na][1] * i0);
        *(__half2*)(ob1 + cp) = __floats2half2_rn(O[na][2] * i1, O[na][3] * i1);
    }
}

extern "C" void kernel_launch(void* const* d_in, const int* in_sizes, int n_in,
                              void* d_out, int out_size) {
    const float* x      = (const float*)d_in[0];
    const float* rpe    = (const float*)d_in[1];
    const float* qkv_w  = (const float*)d_in[2];
    const float* proj_w = (const float*)d_in[3];
    const float* proj_b = (const float*)d_in[4];
    float* out = (float*)d_out;

    preperm<<<(10240 * 32 + 255) / 256, 256>>>(x, qkv_w, proj_w);
    cudaFuncSetAttribute(mma_gemm, cudaFuncAttributeMaxDynamicSharedMemorySize, GEMM_SMEM);
    mma_gemm<<<dim3(64, 12), 256, GEMM_SMEM>>>(nullptr, nullptr, 0);
    attn_mma<<<dim3(8, 8, 8), 256, ATT_SMEM>>>(rpe);
    mma_gemm<<<dim3(64, 4), 256, GEMM_SMEM>>>(proj_b, out, 1);
}